// round 7
// baseline (speedup 1.0000x reference)
#include <cuda_runtime.h>
#include <cuda_fp16.h>

// ---------------------------------------------------------------------------
// Hetero-GNN (5 hetero_conv layers) over N=100000 nodes.
// R7 = R6 (4 nodes/warp, 512-thread blocks, merged CSR build) with
//      __launch_bounds__ to fix the register-pressure launch failure.
// ---------------------------------------------------------------------------

#define N_NODES 100000
#define MAXC 64
#define NPW 4            // nodes per warp

// Scratch (device globals; no allocation allowed)
__device__ __half g_xt16[N_NODES * MAXC];
__device__ __half g_xi16[N_NODES * MAXC];
__device__ float  g_base[N_NODES * MAXC];
__device__ float  g_proj[N_NODES * MAXC];
__device__ float  g_h   [N_NODES * 32];
__device__ float  g_h2  [N_NODES * 32];

__device__ int g_deg_t[N_NODES];
__device__ int g_deg_i[N_NODES];
__device__ int g_rpt  [N_NODES + 1];
__device__ int g_rpi  [N_NODES + 1];
__device__ int g_bsum_t[1024];
__device__ int g_bsum_i[1024];
__device__ int g_col_t[100000];
__device__ int g_col_i[3200000];

// ---------------------------------------------------------------------------
// CSR build (merged kernels)
// ---------------------------------------------------------------------------
__global__ void zero2_kernel(int* __restrict__ a, int* __restrict__ b, int n) {
    int i = blockIdx.x * blockDim.x + threadIdx.x;
    if (i < n) { a[i] = 0; b[i] = 0; }
}

__global__ void count_both(const int* __restrict__ dst_t, int Et,
                           const int* __restrict__ dst_i, int Ei,
                           int* __restrict__ degt, int* __restrict__ degi) {
    int i = blockIdx.x * blockDim.x + threadIdx.x;
    if (i < Et) atomicAdd(&degt[dst_t[i]], 1);
    else if (i < Et + Ei) atomicAdd(&degi[dst_i[i - Et]], 1);
}

__global__ void scan_p1_both(const int* __restrict__ degt, int* __restrict__ rpt,
                             int* __restrict__ bst,
                             const int* __restrict__ degi, int* __restrict__ rpi,
                             int* __restrict__ bsi, int n, int nb) {
    __shared__ int sh[1024];
    bool isT = blockIdx.x < (unsigned)nb;
    const int* deg = isT ? degt : degi;
    int* rowptr    = isT ? rpt  : rpi;
    int* bsum      = isT ? bst  : bsi;
    int blk = isT ? blockIdx.x : (blockIdx.x - nb);

    int i = blk * 1024 + threadIdx.x;
    int v = (i < n) ? deg[i] : 0;
    sh[threadIdx.x] = v;
    __syncthreads();
    for (int off = 1; off < 1024; off <<= 1) {
        int t = (threadIdx.x >= off) ? sh[threadIdx.x - off] : 0;
        __syncthreads();
        sh[threadIdx.x] += t;
        __syncthreads();
    }
    if (i < n) rowptr[i] = sh[threadIdx.x] - v;
    if (threadIdx.x == 1023) bsum[blk] = sh[1023];
}

__global__ void scan_p2_both(int* __restrict__ bst, int* __restrict__ bsi, int nb) {
    __shared__ int sh[1024];
    int* bsum = (blockIdx.x == 0) ? bst : bsi;
    int v = (threadIdx.x < nb) ? bsum[threadIdx.x] : 0;
    sh[threadIdx.x] = v;
    __syncthreads();
    for (int off = 1; off < 1024; off <<= 1) {
        int t = (threadIdx.x >= off) ? sh[threadIdx.x - off] : 0;
        __syncthreads();
        sh[threadIdx.x] += t;
        __syncthreads();
    }
    if (threadIdx.x < nb) bsum[threadIdx.x] = sh[threadIdx.x] - v;
}

__global__ void scan_p3_both(int* __restrict__ rpt, const int* __restrict__ bst,
                             int* __restrict__ curt, int Et,
                             int* __restrict__ rpi, const int* __restrict__ bsi,
                             int* __restrict__ curi, int Ei, int n) {
    int i = blockIdx.x * blockDim.x + threadIdx.x;
    if (i < n) {
        int v = rpt[i] + bst[i >> 10];
        rpt[i] = v; curt[i] = v;
    } else if (i < 2 * n) {
        int j = i - n;
        int v = rpi[j] + bsi[j >> 10];
        rpi[j] = v; curi[j] = v;
    }
    if (i == 0) { rpt[n] = Et; rpi[n] = Ei; }
}

__global__ void fill_both(const int* __restrict__ ei_t, int Et,
                          const int* __restrict__ ei_i, int Ei,
                          int* __restrict__ curt, int* __restrict__ colt,
                          int* __restrict__ curi, int* __restrict__ coli) {
    int i = blockIdx.x * blockDim.x + threadIdx.x;
    if (i < Et) {
        int d = ei_t[Et + i];
        int p = atomicAdd(&curt[d], 1);
        colt[p] = ei_t[i];
    } else if (i < Et + Ei) {
        int j = i - Et;
        int d = ei_i[Ei + j];
        int p = atomicAdd(&curi[d], 1);
        coli[p] = ei_i[j];
    }
}

// ---------------------------------------------------------------------------
// Transform: xt16 = fp16(x@Wt), xi16 = fp16(x@Wi), base = x@Wr + b [, proj]
// 4 nodes per warp, 512-thread blocks.
// ---------------------------------------------------------------------------
template<int CIN, int COUT, bool PROJ>
__global__ void __launch_bounds__(512, 1)
transform_kernel(const float* __restrict__ x,
                 const float* __restrict__ Wt,
                 const float* __restrict__ Wi,
                 const float* __restrict__ Wr,
                 const float* __restrict__ b,
                 const float* __restrict__ Wp,
                 __half* __restrict__ xt16,
                 __half* __restrict__ xi16,
                 float* __restrict__ base,
                 float* __restrict__ proj,
                 int n) {
    __shared__ float sWt[CIN * COUT];
    __shared__ float sWi[CIN * COUT];
    __shared__ float sWr[CIN * COUT];
    __shared__ float sWp[PROJ ? (CIN * COUT) : 1];
    __shared__ float sB[COUT];
    for (int i = threadIdx.x; i < CIN * COUT; i += blockDim.x) {
        sWt[i] = Wt[i]; sWi[i] = Wi[i]; sWr[i] = Wr[i];
        if (PROJ) sWp[i] = Wp[i];
    }
    for (int i = threadIdx.x; i < COUT; i += blockDim.x) sB[i] = b[i];
    __syncthreads();

    int warp  = blockIdx.x * (blockDim.x >> 5) + (threadIdx.x >> 5);
    int lane  = threadIdx.x & 31;
    int node0 = warp * NPW;

    for (int u = 0; u < NPW; u++) {
        int node = node0 + u;
        if (node >= n) break;

        float xr[CIN];
#pragma unroll
        for (int ci = 0; ci < CIN; ci++) xr[ci] = x[node * CIN + ci];

        constexpr int R = (COUT + 31) / 32;
#pragma unroll
        for (int r = 0; r < R; r++) {
            int co = lane + 32 * r;
            float at = 0.f, ai = 0.f, ar = sB[co], ap = 0.f;
#pragma unroll
            for (int ci = 0; ci < CIN; ci++) {
                float xv = xr[ci];
                at = fmaf(xv, sWt[ci * COUT + co], at);
                ai = fmaf(xv, sWi[ci * COUT + co], ai);
                ar = fmaf(xv, sWr[ci * COUT + co], ar);
                if (PROJ) ap = fmaf(xv, sWp[ci * COUT + co], ap);
            }
            xt16[node * COUT + co] = __float2half(at);
            xi16[node * COUT + co] = __float2half(ai);
            base[node * COUT + co] = ar;
            if (PROJ) proj[node * COUT + co] = ap;
        }
    }
}

// ---------------------------------------------------------------------------
// Aggregation, C=32. 4 nodes/warp, lane = channel (fp16 load, fp32 acc).
// ---------------------------------------------------------------------------
template<int MODE>
__global__ void __launch_bounds__(512, 1)
agg32_kernel(const __half* __restrict__ xt16, const __half* __restrict__ xi16,
             const float* __restrict__ base,
             const int* __restrict__ rpt, const int* __restrict__ colt,
             const int* __restrict__ rpi, const int* __restrict__ coli,
             const float* __restrict__ extra,
             float* __restrict__ out, int n) {
    int warp  = blockIdx.x * (blockDim.x >> 5) + (threadIdx.x >> 5);
    int lane  = threadIdx.x & 31;
    int node0 = warp * NPW;

    for (int u = 0; u < NPW; u++) {
        int node = node0 + u;
        if (node >= n) break;

        float st = 0.f, si = 0.f;

        int b0 = rpt[node], e0 = rpt[node + 1];
        for (int e = b0; e < e0; e++) {
            int s = colt[e];
            st += __half2float(xt16[s * 32 + lane]);
        }

        int b1 = rpi[node], e1 = rpi[node + 1];
        int e = b1;
        for (; e + 32 <= e1; e += 32) {
            int idx = coli[e + lane];
#pragma unroll
            for (int k = 0; k < 32; k++) {
                int s = __shfl_sync(0xffffffffu, idx, k);
                si += __half2float(xi16[s * 32 + lane]);
            }
        }
        if (e < e1) {
            int rem = e1 - e;
            int idx = (lane < rem) ? coli[e + lane] : 0;
            for (int k = 0; k < rem; k++) {
                int s = __shfl_sync(0xffffffffu, idx, k);
                si += __half2float(xi16[s * 32 + lane]);
            }
        }

        float deg = (float)(e1 - b1);
        float v = st + si / fmaxf(deg, 1.0f) + base[node * 32 + lane];
        v = fmaxf(v, 0.0f);
        if (MODE == 1) v += extra[node * 32 + lane];
        out[node * 32 + lane] = v;
    }
}

// ---------------------------------------------------------------------------
// Aggregation, C=64 (last layer). 4 nodes/warp, __half2 per lane.
// ---------------------------------------------------------------------------
__global__ void __launch_bounds__(512, 1)
agg64_kernel(const __half* __restrict__ xt16, const __half* __restrict__ xi16,
             const float* __restrict__ base,
             const int* __restrict__ rpt, const int* __restrict__ colt,
             const int* __restrict__ rpi, const int* __restrict__ coli,
             const float* __restrict__ extra,
             float* __restrict__ out, int n) {
    int warp  = blockIdx.x * (blockDim.x >> 5) + (threadIdx.x >> 5);
    int lane  = threadIdx.x & 31;
    int node0 = warp * NPW;

    const __half2* xt2 = (const __half2*)xt16;
    const __half2* xi2 = (const __half2*)xi16;

    for (int u = 0; u < NPW; u++) {
        int node = node0 + u;
        if (node >= n) break;

        float2 st = make_float2(0.f, 0.f), si = make_float2(0.f, 0.f);

        int b0 = rpt[node], e0 = rpt[node + 1];
        for (int e = b0; e < e0; e++) {
            int s = colt[e];
            float2 v = __half22float2(xt2[s * 32 + lane]);
            st.x += v.x; st.y += v.y;
        }

        int b1 = rpi[node], e1 = rpi[node + 1];
        int e = b1;
        for (; e + 32 <= e1; e += 32) {
            int idx = coli[e + lane];
#pragma unroll
            for (int k = 0; k < 32; k++) {
                int s = __shfl_sync(0xffffffffu, idx, k);
                float2 v = __half22float2(xi2[s * 32 + lane]);
                si.x += v.x; si.y += v.y;
            }
        }
        if (e < e1) {
            int rem = e1 - e;
            int idx = (lane < rem) ? coli[e + lane] : 0;
            for (int k = 0; k < rem; k++) {
                int s = __shfl_sync(0xffffffffu, idx, k);
                float2 v = __half22float2(xi2[s * 32 + lane]);
                si.x += v.x; si.y += v.y;
            }
        }

        float inv = 1.0f / fmaxf((float)(e1 - b1), 1.0f);
        float2 bs = ((const float2*)base)[node * 32 + lane];
        float2 ex = ((const float2*)extra)[node * 32 + lane];
        float2 r;
        r.x = fmaxf(st.x + si.x * inv + bs.x, 0.0f) + ex.x;
        r.y = fmaxf(st.y + si.y * inv + bs.y, 0.0f) + ex.y;
        ((float2*)out)[node * 32 + lane] = r;
    }
}

// ---------------------------------------------------------------------------
// Launch
// ---------------------------------------------------------------------------
extern "C" void kernel_launch(void* const* d_in, const int* in_sizes, int n_in,
                              void* d_out, int out_size) {
    const float* x        = (const float*)d_in[0];
    const int*   ei_t     = (const int*)d_in[1];
    const int*   ei_i     = (const int*)d_in[2];
    const float* head_Wt  = (const float*)d_in[3];
    const float* head_Wi  = (const float*)d_in[4];
    const float* head_Wr  = (const float*)d_in[5];
    const float* head_b   = (const float*)d_in[6];
    const float* blk_Wt   = (const float*)d_in[7];
    const float* blk_Wi   = (const float*)d_in[8];
    const float* blk_Wr   = (const float*)d_in[9];
    const float* blk_b    = (const float*)d_in[10];
    const float* last_Wt  = (const float*)d_in[11];
    const float* last_Wi  = (const float*)d_in[12];
    const float* last_Wr  = (const float*)d_in[13];
    const float* last_b   = (const float*)d_in[14];
    const float* last_proj= (const float*)d_in[15];

    const int n  = in_sizes[0] / 6;      // 100000
    const int Et = in_sizes[1] / 2;      // 100000
    const int Ei = in_sizes[2] / 2;      // 3200000

    float *base, *proj, *h, *h2;
    __half *xt16, *xi16;
    int *degt, *degi, *rpt, *rpi, *colt, *coli, *bst, *bsi;
    cudaGetSymbolAddress((void**)&xt16, g_xt16);
    cudaGetSymbolAddress((void**)&xi16, g_xi16);
    cudaGetSymbolAddress((void**)&base, g_base);
    cudaGetSymbolAddress((void**)&proj, g_proj);
    cudaGetSymbolAddress((void**)&h,    g_h);
    cudaGetSymbolAddress((void**)&h2,   g_h2);
    cudaGetSymbolAddress((void**)&degt, g_deg_t);
    cudaGetSymbolAddress((void**)&degi, g_deg_i);
    cudaGetSymbolAddress((void**)&rpt,  g_rpt);
    cudaGetSymbolAddress((void**)&rpi,  g_rpi);
    cudaGetSymbolAddress((void**)&bst,  g_bsum_t);
    cudaGetSymbolAddress((void**)&bsi,  g_bsum_i);
    cudaGetSymbolAddress((void**)&colt, g_col_t);
    cudaGetSymbolAddress((void**)&coli, g_col_i);

    const int T = 256;
    const int TB = 512;                            // node-kernel block size
    const int nodesPerBlock = (TB / 32) * NPW;     // 16 warps * 4 = 64
    int nodeBlocks = (n + nodesPerBlock - 1) / nodesPerBlock;   // 1563
    int nb = (n + 1023) / 1024;
    int Eall = Et + Ei;

    // --- CSR build (6 launches) ---
    zero2_kernel<<<(n + T - 1) / T, T>>>(degt, degi, n);
    count_both<<<(Eall + T - 1) / T, T>>>(ei_t + Et, Et, ei_i + Ei, Ei, degt, degi);
    scan_p1_both<<<2 * nb, 1024>>>(degt, rpt, bst, degi, rpi, bsi, n, nb);
    scan_p2_both<<<2, 1024>>>(bst, bsi, nb);
    scan_p3_both<<<(2 * n + T - 1) / T, T>>>(rpt, bst, degt, Et, rpi, bsi, degi, Ei, n);
    fill_both<<<(Eall + T - 1) / T, T>>>(ei_t, Et, ei_i, Ei, degt, colt, degi, coli);

    // --- head: 6 -> 32, relu ---
    transform_kernel<6, 32, false><<<nodeBlocks, TB>>>(
        x, head_Wt, head_Wi, head_Wr, head_b, nullptr,
        xt16, xi16, base, nullptr, n);
    agg32_kernel<0><<<nodeBlocks, TB>>>(xt16, xi16, base, rpt, colt, rpi, coli,
                                        nullptr, h, n);

    // --- 3 residual blocks: 32 -> 32, h = relu(conv(h)) + h ---
    for (int i = 0; i < 3; i++) {
        transform_kernel<32, 32, false><<<nodeBlocks, TB>>>(
            h, blk_Wt + i * 32 * 32, blk_Wi + i * 32 * 32,
            blk_Wr + i * 32 * 32, blk_b + i * 32, nullptr,
            xt16, xi16, base, nullptr, n);
        agg32_kernel<1><<<nodeBlocks, TB>>>(xt16, xi16, base, rpt, colt, rpi, coli,
                                            h, h2, n);
        float* tmp = h; h = h2; h2 = tmp;
    }

    // --- last: 32 -> 64, out = relu(conv(h)) + h @ last_proj ---
    transform_kernel<32, 64, true><<<nodeBlocks, TB>>>(
        h, last_Wt, last_Wi, last_Wr, last_b, last_proj,
        xt16, xi16, base, proj, n);
    agg64_kernel<<<nodeBlocks, TB>>>(xt16, xi16, base, rpt, colt, rpi, coli,
                                     proj, (float*)d_out, n);
}

// round 8
// speedup vs baseline: 1.0881x; 1.0881x over previous
#include <cuda_runtime.h>
#include <cuda_fp16.h>

// ---------------------------------------------------------------------------
// Hetero-GNN (5 hetero_conv layers) over N=100000 nodes.
// R8 = R4 (best: 678us) with ONE change: remainder gather loops replaced by
//      unrolled predicated 8-edge blocks (MLP 1 -> 8, over-fetch <= 7 edges).
// ---------------------------------------------------------------------------

#define N_NODES 100000
#define MAXC 64

// Scratch (device globals; no allocation allowed)
__device__ __half g_xt16[N_NODES * MAXC];
__device__ __half g_xi16[N_NODES * MAXC];
__device__ float  g_base[N_NODES * MAXC];
__device__ float  g_proj[N_NODES * MAXC];
__device__ float  g_h   [N_NODES * 32];
__device__ float  g_h2  [N_NODES * 32];

__device__ int g_deg_t[N_NODES];
__device__ int g_deg_i[N_NODES];
__device__ int g_rpt  [N_NODES + 1];
__device__ int g_rpi  [N_NODES + 1];
__device__ int g_bsum_t[1024];
__device__ int g_bsum_i[1024];
__device__ int g_col_t[100000];
__device__ int g_col_i[3200000];

// ---------------------------------------------------------------------------
// CSR build (R4 layout: per-relation kernels)
// ---------------------------------------------------------------------------
__global__ void zero2_kernel(int* __restrict__ a, int* __restrict__ b, int n) {
    int i = blockIdx.x * blockDim.x + threadIdx.x;
    if (i < n) { a[i] = 0; b[i] = 0; }
}

__global__ void count_kernel(const int* __restrict__ dst, int E, int* __restrict__ deg) {
    int i = blockIdx.x * blockDim.x + threadIdx.x;
    if (i < E) atomicAdd(&deg[dst[i]], 1);
}

__global__ void scan_p1(const int* __restrict__ deg, int* __restrict__ rowptr,
                        int* __restrict__ bsum, int n) {
    __shared__ int sh[1024];
    int i = blockIdx.x * 1024 + threadIdx.x;
    int v = (i < n) ? deg[i] : 0;
    sh[threadIdx.x] = v;
    __syncthreads();
    for (int off = 1; off < 1024; off <<= 1) {
        int t = (threadIdx.x >= off) ? sh[threadIdx.x - off] : 0;
        __syncthreads();
        sh[threadIdx.x] += t;
        __syncthreads();
    }
    if (i < n) rowptr[i] = sh[threadIdx.x] - v;
    if (threadIdx.x == 1023) bsum[blockIdx.x] = sh[1023];
}

__global__ void scan_p2(int* __restrict__ bsum, int nb) {
    __shared__ int sh[1024];
    int v = (threadIdx.x < nb) ? bsum[threadIdx.x] : 0;
    sh[threadIdx.x] = v;
    __syncthreads();
    for (int off = 1; off < 1024; off <<= 1) {
        int t = (threadIdx.x >= off) ? sh[threadIdx.x - off] : 0;
        __syncthreads();
        sh[threadIdx.x] += t;
        __syncthreads();
    }
    if (threadIdx.x < nb) bsum[threadIdx.x] = sh[threadIdx.x] - v;
}

__global__ void scan_p3(int* __restrict__ rowptr, const int* __restrict__ bsum,
                        int* __restrict__ cursor, int n, int E) {
    int i = blockIdx.x * blockDim.x + threadIdx.x;
    if (i < n) {
        int v = rowptr[i] + bsum[i >> 10];
        rowptr[i] = v;
        cursor[i] = v;
    }
    if (i == 0) rowptr[n] = E;
}

__global__ void fill_kernel(const int* __restrict__ src, const int* __restrict__ dst,
                            int E, int* __restrict__ cursor, int* __restrict__ col) {
    int i = blockIdx.x * blockDim.x + threadIdx.x;
    if (i < E) {
        int d = dst[i];
        int p = atomicAdd(&cursor[d], 1);
        col[p] = src[i];
    }
}

// ---------------------------------------------------------------------------
// Transform: xt16 = fp16(x@Wt), xi16 = fp16(x@Wi), base = x@Wr + b [, proj]
// ---------------------------------------------------------------------------
template<int CIN, int COUT, bool PROJ>
__global__ void transform_kernel(const float* __restrict__ x,
                                 const float* __restrict__ Wt,
                                 const float* __restrict__ Wi,
                                 const float* __restrict__ Wr,
                                 const float* __restrict__ b,
                                 const float* __restrict__ Wp,
                                 __half* __restrict__ xt16,
                                 __half* __restrict__ xi16,
                                 float* __restrict__ base,
                                 float* __restrict__ proj,
                                 int n) {
    __shared__ float sWt[CIN * COUT];
    __shared__ float sWi[CIN * COUT];
    __shared__ float sWr[CIN * COUT];
    __shared__ float sWp[PROJ ? (CIN * COUT) : 1];
    __shared__ float sB[COUT];
    for (int i = threadIdx.x; i < CIN * COUT; i += blockDim.x) {
        sWt[i] = Wt[i]; sWi[i] = Wi[i]; sWr[i] = Wr[i];
        if (PROJ) sWp[i] = Wp[i];
    }
    for (int i = threadIdx.x; i < COUT; i += blockDim.x) sB[i] = b[i];
    __syncthreads();

    int node = blockIdx.x * (blockDim.x >> 5) + (threadIdx.x >> 5);
    if (node >= n) return;
    int lane = threadIdx.x & 31;

    float xr[CIN];
#pragma unroll
    for (int ci = 0; ci < CIN; ci++) xr[ci] = x[node * CIN + ci];

    constexpr int R = (COUT + 31) / 32;
#pragma unroll
    for (int r = 0; r < R; r++) {
        int co = lane + 32 * r;
        float at = 0.f, ai = 0.f, ar = sB[co], ap = 0.f;
#pragma unroll
        for (int ci = 0; ci < CIN; ci++) {
            float xv = xr[ci];
            at = fmaf(xv, sWt[ci * COUT + co], at);
            ai = fmaf(xv, sWi[ci * COUT + co], ai);
            ar = fmaf(xv, sWr[ci * COUT + co], ar);
            if (PROJ) ap = fmaf(xv, sWp[ci * COUT + co], ap);
        }
        xt16[node * COUT + co] = __float2half(at);
        xi16[node * COUT + co] = __float2half(ai);
        base[node * COUT + co] = ar;
        if (PROJ) proj[node * COUT + co] = ap;
    }
}

// ---------------------------------------------------------------------------
// Aggregation, C=32. warp-per-node, lane = channel (fp16 load, fp32 acc).
// Full 32-chunks + PREDICATED UNROLLED 8-blocks for the remainder (MLP=8).
// ---------------------------------------------------------------------------
template<int MODE>
__global__ void agg32_kernel(const __half* __restrict__ xt16, const __half* __restrict__ xi16,
                             const float* __restrict__ base,
                             const int* __restrict__ rpt, const int* __restrict__ colt,
                             const int* __restrict__ rpi, const int* __restrict__ coli,
                             const float* __restrict__ extra,
                             float* __restrict__ out, int n) {
    int node = blockIdx.x * (blockDim.x >> 5) + (threadIdx.x >> 5);
    if (node >= n) return;
    int lane = threadIdx.x & 31;

    float st = 0.f, si = 0.f;

    // temp relation (deg ~Poisson(1)): predicated 4-blocks
    int b0 = rpt[node], e0 = rpt[node + 1];
    int dt = e0 - b0;
    if (dt > 0) {
        int last = e0 - 1;
        int p = b0 + lane;
        int idx = colt[p < last ? p : last];
        for (int k0 = 0; k0 < dt; k0 += 4) {
#pragma unroll
            for (int kk = 0; kk < 4; kk++) {
                int k = k0 + kk;
                int kc = k < dt ? k : dt - 1;
                int s = __shfl_sync(0xffffffffu, idx, kc);
                float v = __half2float(xt16[s * 32 + lane]);
                st += (k < dt) ? v : 0.f;
            }
        }
    }

    // inter relation (mean): full 32-chunks, then predicated 8-blocks
    int b1 = rpi[node], e1 = rpi[node + 1];
    int e = b1;
    for (; e + 32 <= e1; e += 32) {
        int idx = coli[e + lane];
#pragma unroll
        for (int k = 0; k < 32; k++) {
            int s = __shfl_sync(0xffffffffu, idx, k);
            si += __half2float(xi16[s * 32 + lane]);
        }
    }
    int m = e1 - e;
    if (m > 0) {
        int last = e1 - 1;
        int p = e + lane;
        int idx = coli[p < last ? p : last];
        for (int k0 = 0; k0 < m; k0 += 8) {
#pragma unroll
            for (int kk = 0; kk < 8; kk++) {
                int k = k0 + kk;
                int kc = k < m ? k : m - 1;
                int s = __shfl_sync(0xffffffffu, idx, kc);
                float v = __half2float(xi16[s * 32 + lane]);
                si += (k < m) ? v : 0.f;
            }
        }
    }

    float deg = (float)(e1 - b1);
    float v = st + si / fmaxf(deg, 1.0f) + base[node * 32 + lane];
    v = fmaxf(v, 0.0f);
    if (MODE == 1) v += extra[node * 32 + lane];
    out[node * 32 + lane] = v;
}

// ---------------------------------------------------------------------------
// Aggregation, C=64 (last layer). __half2 per lane; same loop structure.
// ---------------------------------------------------------------------------
__global__ void agg64_kernel(const __half* __restrict__ xt16, const __half* __restrict__ xi16,
                             const float* __restrict__ base,
                             const int* __restrict__ rpt, const int* __restrict__ colt,
                             const int* __restrict__ rpi, const int* __restrict__ coli,
                             const float* __restrict__ extra,
                             float* __restrict__ out, int n) {
    int node = blockIdx.x * (blockDim.x >> 5) + (threadIdx.x >> 5);
    if (node >= n) return;
    int lane = threadIdx.x & 31;

    const __half2* xt2 = (const __half2*)xt16;
    const __half2* xi2 = (const __half2*)xi16;

    float2 st = make_float2(0.f, 0.f), si = make_float2(0.f, 0.f);

    int b0 = rpt[node], e0 = rpt[node + 1];
    int dt = e0 - b0;
    if (dt > 0) {
        int last = e0 - 1;
        int p = b0 + lane;
        int idx = colt[p < last ? p : last];
        for (int k0 = 0; k0 < dt; k0 += 4) {
#pragma unroll
            for (int kk = 0; kk < 4; kk++) {
                int k = k0 + kk;
                int kc = k < dt ? k : dt - 1;
                int s = __shfl_sync(0xffffffffu, idx, kc);
                float2 v = __half22float2(xt2[s * 32 + lane]);
                bool on = (k < dt);
                st.x += on ? v.x : 0.f;
                st.y += on ? v.y : 0.f;
            }
        }
    }

    int b1 = rpi[node], e1 = rpi[node + 1];
    int e = b1;
    for (; e + 32 <= e1; e += 32) {
        int idx = coli[e + lane];
#pragma unroll
        for (int k = 0; k < 32; k++) {
            int s = __shfl_sync(0xffffffffu, idx, k);
            float2 v = __half22float2(xi2[s * 32 + lane]);
            si.x += v.x; si.y += v.y;
        }
    }
    int m = e1 - e;
    if (m > 0) {
        int last = e1 - 1;
        int p = e + lane;
        int idx = coli[p < last ? p : last];
        for (int k0 = 0; k0 < m; k0 += 8) {
#pragma unroll
            for (int kk = 0; kk < 8; kk++) {
                int k = k0 + kk;
                int kc = k < m ? k : m - 1;
                int s = __shfl_sync(0xffffffffu, idx, kc);
                float2 v = __half22float2(xi2[s * 32 + lane]);
                bool on = (k < m);
                si.x += on ? v.x : 0.f;
                si.y += on ? v.y : 0.f;
            }
        }
    }

    float inv = 1.0f / fmaxf((float)(e1 - b1), 1.0f);
    float2 bs = ((const float2*)base)[node * 32 + lane];
    float2 ex = ((const float2*)extra)[node * 32 + lane];
    float2 r;
    r.x = fmaxf(st.x + si.x * inv + bs.x, 0.0f) + ex.x;
    r.y = fmaxf(st.y + si.y * inv + bs.y, 0.0f) + ex.y;
    ((float2*)out)[node * 32 + lane] = r;
}

// ---------------------------------------------------------------------------
// Launch
// ---------------------------------------------------------------------------
extern "C" void kernel_launch(void* const* d_in, const int* in_sizes, int n_in,
                              void* d_out, int out_size) {
    const float* x        = (const float*)d_in[0];
    const int*   ei_t     = (const int*)d_in[1];
    const int*   ei_i     = (const int*)d_in[2];
    const float* head_Wt  = (const float*)d_in[3];
    const float* head_Wi  = (const float*)d_in[4];
    const float* head_Wr  = (const float*)d_in[5];
    const float* head_b   = (const float*)d_in[6];
    const float* blk_Wt   = (const float*)d_in[7];
    const float* blk_Wi   = (const float*)d_in[8];
    const float* blk_Wr   = (const float*)d_in[9];
    const float* blk_b    = (const float*)d_in[10];
    const float* last_Wt  = (const float*)d_in[11];
    const float* last_Wi  = (const float*)d_in[12];
    const float* last_Wr  = (const float*)d_in[13];
    const float* last_b   = (const float*)d_in[14];
    const float* last_proj= (const float*)d_in[15];

    const int n  = in_sizes[0] / 6;      // 100000
    const int Et = in_sizes[1] / 2;      // 100000
    const int Ei = in_sizes[2] / 2;      // 3200000

    float *base, *proj, *h, *h2;
    __half *xt16, *xi16;
    int *degt, *degi, *rpt, *rpi, *colt, *coli, *bst, *bsi;
    cudaGetSymbolAddress((void**)&xt16, g_xt16);
    cudaGetSymbolAddress((void**)&xi16, g_xi16);
    cudaGetSymbolAddress((void**)&base, g_base);
    cudaGetSymbolAddress((void**)&proj, g_proj);
    cudaGetSymbolAddress((void**)&h,    g_h);
    cudaGetSymbolAddress((void**)&h2,   g_h2);
    cudaGetSymbolAddress((void**)&degt, g_deg_t);
    cudaGetSymbolAddress((void**)&degi, g_deg_i);
    cudaGetSymbolAddress((void**)&rpt,  g_rpt);
    cudaGetSymbolAddress((void**)&rpi,  g_rpi);
    cudaGetSymbolAddress((void**)&bst,  g_bsum_t);
    cudaGetSymbolAddress((void**)&bsi,  g_bsum_i);
    cudaGetSymbolAddress((void**)&colt, g_col_t);
    cudaGetSymbolAddress((void**)&coli, g_col_i);

    const int T = 256;
    int nodeBlocks = (n * 32 + T - 1) / T;
    int nb = (n + 1023) / 1024;

    // --- CSR build ---
    zero2_kernel<<<(n + T - 1) / T, T>>>(degt, degi, n);
    count_kernel<<<(Et + T - 1) / T, T>>>(ei_t + Et, Et, degt);
    count_kernel<<<(Ei + T - 1) / T, T>>>(ei_i + Ei, Ei, degi);
    scan_p1<<<nb, 1024>>>(degt, rpt, bst, n);
    scan_p1<<<nb, 1024>>>(degi, rpi, bsi, n);
    scan_p2<<<1, 1024>>>(bst, nb);
    scan_p2<<<1, 1024>>>(bsi, nb);
    scan_p3<<<(n + T) / T, T>>>(rpt, bst, degt, n, Et);
    scan_p3<<<(n + T) / T, T>>>(rpi, bsi, degi, n, Ei);
    fill_kernel<<<(Et + T - 1) / T, T>>>(ei_t, ei_t + Et, Et, degt, colt);
    fill_kernel<<<(Ei + T - 1) / T, T>>>(ei_i, ei_i + Ei, Ei, degi, coli);

    // --- head: 6 -> 32, relu ---
    transform_kernel<6, 32, false><<<nodeBlocks, T>>>(
        x, head_Wt, head_Wi, head_Wr, head_b, nullptr,
        xt16, xi16, base, nullptr, n);
    agg32_kernel<0><<<nodeBlocks, T>>>(xt16, xi16, base, rpt, colt, rpi, coli,
                                       nullptr, h, n);

    // --- 3 residual blocks: 32 -> 32, h = relu(conv(h)) + h ---
    for (int i = 0; i < 3; i++) {
        transform_kernel<32, 32, false><<<nodeBlocks, T>>>(
            h, blk_Wt + i * 32 * 32, blk_Wi + i * 32 * 32,
            blk_Wr + i * 32 * 32, blk_b + i * 32, nullptr,
            xt16, xi16, base, nullptr, n);
        agg32_kernel<1><<<nodeBlocks, T>>>(xt16, xi16, base, rpt, colt, rpi, coli,
                                           h, h2, n);
        float* tmp = h; h = h2; h2 = tmp;
    }

    // --- last: 32 -> 64, out = relu(conv(h)) + h @ last_proj ---
    transform_kernel<32, 64, true><<<nodeBlocks, T>>>(
        h, last_Wt, last_Wi, last_Wr, last_b, last_proj,
        xt16, xi16, base, proj, n);
    agg64_kernel<<<nodeBlocks, T>>>(xt16, xi16, base, rpt, colt, rpi, coli,
                                    proj, (float*)d_out, n);
}

// round 9
// speedup vs baseline: 1.1124x; 1.0223x over previous
#include <cuda_runtime.h>
#include <cuda_fp16.h>

// ---------------------------------------------------------------------------
// Hetero-GNN (5 hetero_conv layers) over N=100000 nodes.
// R9 = R4 (best: 678us) with ONE change: atomic counters (degree + fill
//      cursor) padded to one per 128B line (stride 32 ints) to kill
//      sector-level serialization at the LTS atomic ALUs.
// ---------------------------------------------------------------------------

#define N_NODES 100000
#define MAXC 64
#define CPAD 32   // counter stride in ints (128B)

// Scratch (device globals; no allocation allowed)
__device__ __half g_xt16[N_NODES * MAXC];
__device__ __half g_xi16[N_NODES * MAXC];
__device__ float  g_base[N_NODES * MAXC];
__device__ float  g_proj[N_NODES * MAXC];
__device__ float  g_h   [N_NODES * 32];
__device__ float  g_h2  [N_NODES * 32];

__device__ int g_cnt_t[N_NODES * CPAD];   // padded degree counters / fill cursors
__device__ int g_cnt_i[N_NODES * CPAD];
__device__ int g_rpt  [N_NODES + 1];
__device__ int g_rpi  [N_NODES + 1];
__device__ int g_bsum_t[1024];
__device__ int g_bsum_i[1024];
__device__ int g_col_t[100000];
__device__ int g_col_i[3200000];

// ---------------------------------------------------------------------------
// CSR build with padded counters
// ---------------------------------------------------------------------------
__global__ void zero2_kernel(int* __restrict__ a, int* __restrict__ b, int n) {
    int i = blockIdx.x * blockDim.x + threadIdx.x;
    if (i < n) { a[i * CPAD] = 0; b[i * CPAD] = 0; }
}

__global__ void count_kernel(const int* __restrict__ dst, int E, int* __restrict__ cnt) {
    int i = blockIdx.x * blockDim.x + threadIdx.x;
    if (i < E) atomicAdd(&cnt[dst[i] * CPAD], 1);
}

// P1: per-1024-tile exclusive scan of padded counters -> rowptr; totals -> bsum
__global__ void scan_p1(const int* __restrict__ cnt, int* __restrict__ rowptr,
                        int* __restrict__ bsum, int n) {
    __shared__ int sh[1024];
    int i = blockIdx.x * 1024 + threadIdx.x;
    int v = (i < n) ? cnt[i * CPAD] : 0;
    sh[threadIdx.x] = v;
    __syncthreads();
    for (int off = 1; off < 1024; off <<= 1) {
        int t = (threadIdx.x >= off) ? sh[threadIdx.x - off] : 0;
        __syncthreads();
        sh[threadIdx.x] += t;
        __syncthreads();
    }
    if (i < n) rowptr[i] = sh[threadIdx.x] - v;
    if (threadIdx.x == 1023) bsum[blockIdx.x] = sh[1023];
}

__global__ void scan_p2(int* __restrict__ bsum, int nb) {
    __shared__ int sh[1024];
    int v = (threadIdx.x < nb) ? bsum[threadIdx.x] : 0;
    sh[threadIdx.x] = v;
    __syncthreads();
    for (int off = 1; off < 1024; off <<= 1) {
        int t = (threadIdx.x >= off) ? sh[threadIdx.x - off] : 0;
        __syncthreads();
        sh[threadIdx.x] += t;
        __syncthreads();
    }
    if (threadIdx.x < nb) bsum[threadIdx.x] = sh[threadIdx.x] - v;
}

// P3: finalize rowptr and mirror into padded cursors.
__global__ void scan_p3(int* __restrict__ rowptr, const int* __restrict__ bsum,
                        int* __restrict__ cursor, int n, int E) {
    int i = blockIdx.x * blockDim.x + threadIdx.x;
    if (i < n) {
        int v = rowptr[i] + bsum[i >> 10];
        rowptr[i] = v;
        cursor[i * CPAD] = v;
    }
    if (i == 0) rowptr[n] = E;
}

__global__ void fill_kernel(const int* __restrict__ src, const int* __restrict__ dst,
                            int E, int* __restrict__ cursor, int* __restrict__ col) {
    int i = blockIdx.x * blockDim.x + threadIdx.x;
    if (i < E) {
        int d = dst[i];
        int p = atomicAdd(&cursor[d * CPAD], 1);
        col[p] = src[i];
    }
}

// ---------------------------------------------------------------------------
// Transform: xt16 = fp16(x@Wt), xi16 = fp16(x@Wi), base = x@Wr + b [, proj]
// ---------------------------------------------------------------------------
template<int CIN, int COUT, bool PROJ>
__global__ void transform_kernel(const float* __restrict__ x,
                                 const float* __restrict__ Wt,
                                 const float* __restrict__ Wi,
                                 const float* __restrict__ Wr,
                                 const float* __restrict__ b,
                                 const float* __restrict__ Wp,
                                 __half* __restrict__ xt16,
                                 __half* __restrict__ xi16,
                                 float* __restrict__ base,
                                 float* __restrict__ proj,
                                 int n) {
    __shared__ float sWt[CIN * COUT];
    __shared__ float sWi[CIN * COUT];
    __shared__ float sWr[CIN * COUT];
    __shared__ float sWp[PROJ ? (CIN * COUT) : 1];
    __shared__ float sB[COUT];
    for (int i = threadIdx.x; i < CIN * COUT; i += blockDim.x) {
        sWt[i] = Wt[i]; sWi[i] = Wi[i]; sWr[i] = Wr[i];
        if (PROJ) sWp[i] = Wp[i];
    }
    for (int i = threadIdx.x; i < COUT; i += blockDim.x) sB[i] = b[i];
    __syncthreads();

    int node = blockIdx.x * (blockDim.x >> 5) + (threadIdx.x >> 5);
    if (node >= n) return;
    int lane = threadIdx.x & 31;

    float xr[CIN];
#pragma unroll
    for (int ci = 0; ci < CIN; ci++) xr[ci] = x[node * CIN + ci];

    constexpr int R = (COUT + 31) / 32;
#pragma unroll
    for (int r = 0; r < R; r++) {
        int co = lane + 32 * r;
        float at = 0.f, ai = 0.f, ar = sB[co], ap = 0.f;
#pragma unroll
        for (int ci = 0; ci < CIN; ci++) {
            float xv = xr[ci];
            at = fmaf(xv, sWt[ci * COUT + co], at);
            ai = fmaf(xv, sWi[ci * COUT + co], ai);
            ar = fmaf(xv, sWr[ci * COUT + co], ar);
            if (PROJ) ap = fmaf(xv, sWp[ci * COUT + co], ap);
        }
        xt16[node * COUT + co] = __float2half(at);
        xi16[node * COUT + co] = __float2half(ai);
        base[node * COUT + co] = ar;
        if (PROJ) proj[node * COUT + co] = ap;
    }
}

// ---------------------------------------------------------------------------
// Aggregation, C=32 (R4 body). warp-per-node, lane = channel.
// ---------------------------------------------------------------------------
template<int MODE>
__global__ void agg32_kernel(const __half* __restrict__ xt16, const __half* __restrict__ xi16,
                             const float* __restrict__ base,
                             const int* __restrict__ rpt, const int* __restrict__ colt,
                             const int* __restrict__ rpi, const int* __restrict__ coli,
                             const float* __restrict__ extra,
                             float* __restrict__ out, int n) {
    int node = blockIdx.x * (blockDim.x >> 5) + (threadIdx.x >> 5);
    if (node >= n) return;
    int lane = threadIdx.x & 31;

    float st = 0.f, si = 0.f;

    int b0 = rpt[node], e0 = rpt[node + 1];
    for (int e = b0; e < e0; e++) {
        int s = colt[e];
        st += __half2float(xt16[s * 32 + lane]);
    }

    int b1 = rpi[node], e1 = rpi[node + 1];
    int e = b1;
    for (; e + 32 <= e1; e += 32) {
        int idx = coli[e + lane];
#pragma unroll
        for (int k = 0; k < 32; k++) {
            int s = __shfl_sync(0xffffffffu, idx, k);
            si += __half2float(xi16[s * 32 + lane]);
        }
    }
    if (e < e1) {
        int rem = e1 - e;
        int idx = (lane < rem) ? coli[e + lane] : 0;
        for (int k = 0; k < rem; k++) {
            int s = __shfl_sync(0xffffffffu, idx, k);
            si += __half2float(xi16[s * 32 + lane]);
        }
    }

    float deg = (float)(e1 - b1);
    float v = st + si / fmaxf(deg, 1.0f) + base[node * 32 + lane];
    v = fmaxf(v, 0.0f);
    if (MODE == 1) v += extra[node * 32 + lane];
    out[node * 32 + lane] = v;
}

// ---------------------------------------------------------------------------
// Aggregation, C=64 (last layer, R4 body). __half2 per lane.
// ---------------------------------------------------------------------------
__global__ void agg64_kernel(const __half* __restrict__ xt16, const __half* __restrict__ xi16,
                             const float* __restrict__ base,
                             const int* __restrict__ rpt, const int* __restrict__ colt,
                             const int* __restrict__ rpi, const int* __restrict__ coli,
                             const float* __restrict__ extra,
                             float* __restrict__ out, int n) {
    int node = blockIdx.x * (blockDim.x >> 5) + (threadIdx.x >> 5);
    if (node >= n) return;
    int lane = threadIdx.x & 31;

    const __half2* xt2 = (const __half2*)xt16;
    const __half2* xi2 = (const __half2*)xi16;

    float2 st = make_float2(0.f, 0.f), si = make_float2(0.f, 0.f);

    int b0 = rpt[node], e0 = rpt[node + 1];
    for (int e = b0; e < e0; e++) {
        int s = colt[e];
        float2 v = __half22float2(xt2[s * 32 + lane]);
        st.x += v.x; st.y += v.y;
    }

    int b1 = rpi[node], e1 = rpi[node + 1];
    int e = b1;
    for (; e + 32 <= e1; e += 32) {
        int idx = coli[e + lane];
#pragma unroll
        for (int k = 0; k < 32; k++) {
            int s = __shfl_sync(0xffffffffu, idx, k);
            float2 v = __half22float2(xi2[s * 32 + lane]);
            si.x += v.x; si.y += v.y;
        }
    }
    if (e < e1) {
        int rem = e1 - e;
        int idx = (lane < rem) ? coli[e + lane] : 0;
        for (int k = 0; k < rem; k++) {
            int s = __shfl_sync(0xffffffffu, idx, k);
            float2 v = __half22float2(xi2[s * 32 + lane]);
            si.x += v.x; si.y += v.y;
        }
    }

    float inv = 1.0f / fmaxf((float)(e1 - b1), 1.0f);
    float2 bs = ((const float2*)base)[node * 32 + lane];
    float2 ex = ((const float2*)extra)[node * 32 + lane];
    float2 r;
    r.x = fmaxf(st.x + si.x * inv + bs.x, 0.0f) + ex.x;
    r.y = fmaxf(st.y + si.y * inv + bs.y, 0.0f) + ex.y;
    ((float2*)out)[node * 32 + lane] = r;
}

// ---------------------------------------------------------------------------
// Launch
// ---------------------------------------------------------------------------
extern "C" void kernel_launch(void* const* d_in, const int* in_sizes, int n_in,
                              void* d_out, int out_size) {
    const float* x        = (const float*)d_in[0];
    const int*   ei_t     = (const int*)d_in[1];
    const int*   ei_i     = (const int*)d_in[2];
    const float* head_Wt  = (const float*)d_in[3];
    const float* head_Wi  = (const float*)d_in[4];
    const float* head_Wr  = (const float*)d_in[5];
    const float* head_b   = (const float*)d_in[6];
    const float* blk_Wt   = (const float*)d_in[7];
    const float* blk_Wi   = (const float*)d_in[8];
    const float* blk_Wr   = (const float*)d_in[9];
    const float* blk_b    = (const float*)d_in[10];
    const float* last_Wt  = (const float*)d_in[11];
    const float* last_Wi  = (const float*)d_in[12];
    const float* last_Wr  = (const float*)d_in[13];
    const float* last_b   = (const float*)d_in[14];
    const float* last_proj= (const float*)d_in[15];

    const int n  = in_sizes[0] / 6;      // 100000
    const int Et = in_sizes[1] / 2;      // 100000
    const int Ei = in_sizes[2] / 2;      // 3200000

    float *base, *proj, *h, *h2;
    __half *xt16, *xi16;
    int *cntt, *cnti, *rpt, *rpi, *colt, *coli, *bst, *bsi;
    cudaGetSymbolAddress((void**)&xt16, g_xt16);
    cudaGetSymbolAddress((void**)&xi16, g_xi16);
    cudaGetSymbolAddress((void**)&base, g_base);
    cudaGetSymbolAddress((void**)&proj, g_proj);
    cudaGetSymbolAddress((void**)&h,    g_h);
    cudaGetSymbolAddress((void**)&h2,   g_h2);
    cudaGetSymbolAddress((void**)&cntt, g_cnt_t);
    cudaGetSymbolAddress((void**)&cnti, g_cnt_i);
    cudaGetSymbolAddress((void**)&rpt,  g_rpt);
    cudaGetSymbolAddress((void**)&rpi,  g_rpi);
    cudaGetSymbolAddress((void**)&bst,  g_bsum_t);
    cudaGetSymbolAddress((void**)&bsi,  g_bsum_i);
    cudaGetSymbolAddress((void**)&colt, g_col_t);
    cudaGetSymbolAddress((void**)&coli, g_col_i);

    const int T = 256;
    int nodeBlocks = (n * 32 + T - 1) / T;
    int nb = (n + 1023) / 1024;

    // --- CSR build (padded counters) ---
    zero2_kernel<<<(n + T - 1) / T, T>>>(cntt, cnti, n);
    count_kernel<<<(Et + T - 1) / T, T>>>(ei_t + Et, Et, cntt);
    count_kernel<<<(Ei + T - 1) / T, T>>>(ei_i + Ei, Ei, cnti);
    scan_p1<<<nb, 1024>>>(cntt, rpt, bst, n);
    scan_p1<<<nb, 1024>>>(cnti, rpi, bsi, n);
    scan_p2<<<1, 1024>>>(bst, nb);
    scan_p2<<<1, 1024>>>(bsi, nb);
    scan_p3<<<(n + T) / T, T>>>(rpt, bst, cntt, n, Et);
    scan_p3<<<(n + T) / T, T>>>(rpi, bsi, cnti, n, Ei);
    fill_kernel<<<(Et + T - 1) / T, T>>>(ei_t, ei_t + Et, Et, cntt, colt);
    fill_kernel<<<(Ei + T - 1) / T, T>>>(ei_i, ei_i + Ei, Ei, cnti, coli);

    // --- head: 6 -> 32, relu ---
    transform_kernel<6, 32, false><<<nodeBlocks, T>>>(
        x, head_Wt, head_Wi, head_Wr, head_b, nullptr,
        xt16, xi16, base, nullptr, n);
    agg32_kernel<0><<<nodeBlocks, T>>>(xt16, xi16, base, rpt, colt, rpi, coli,
                                       nullptr, h, n);

    // --- 3 residual blocks: 32 -> 32, h = relu(conv(h)) + h ---
    for (int i = 0; i < 3; i++) {
        transform_kernel<32, 32, false><<<nodeBlocks, T>>>(
            h, blk_Wt + i * 32 * 32, blk_Wi + i * 32 * 32,
            blk_Wr + i * 32 * 32, blk_b + i * 32, nullptr,
            xt16, xi16, base, nullptr, n);
        agg32_kernel<1><<<nodeBlocks, T>>>(xt16, xi16, base, rpt, colt, rpi, coli,
                                           h, h2, n);
        float* tmp = h; h = h2; h2 = tmp;
    }

    // --- last: 32 -> 64, out = relu(conv(h)) + h @ last_proj ---
    transform_kernel<32, 64, true><<<nodeBlocks, T>>>(
        h, last_Wt, last_Wi, last_Wr, last_b, last_proj,
        xt16, xi16, base, proj, n);
    agg64_kernel<<<nodeBlocks, T>>>(xt16, xi16, base, rpt, colt, rpi, coli,
                                    proj, (float*)d_out, n);
}

// round 10
// speedup vs baseline: 1.1203x; 1.0071x over previous
#include <cuda_runtime.h>
#include <cuda_fp16.h>

// ---------------------------------------------------------------------------
// Hetero-GNN (5 hetero_conv layers) over N=100000 nodes.
// R10: per-layer FULLY FUSED kernels (gather raw h over both relations, then
//      in-register combine with weights). No transformed-message arrays.
//      agg(raw) is valid because segment_sum commutes with the linear maps.
// ---------------------------------------------------------------------------

#define N_NODES 100000

// Scratch (device globals; no allocation allowed)
__device__ float g_h [N_NODES * 32];
__device__ float g_h2[N_NODES * 32];

__device__ int g_deg_t[N_NODES];
__device__ int g_deg_i[N_NODES];
__device__ int g_rpt  [N_NODES + 1];
__device__ int g_rpi  [N_NODES + 1];
__device__ int g_bsum_t[1024];
__device__ int g_bsum_i[1024];
__device__ int g_col_t[100000];
__device__ int g_col_i[3200000];

// ---------------------------------------------------------------------------
// CSR build (identical to the 678us champion, R4)
// ---------------------------------------------------------------------------
__global__ void zero2_kernel(int* __restrict__ a, int* __restrict__ b, int n) {
    int i = blockIdx.x * blockDim.x + threadIdx.x;
    if (i < n) { a[i] = 0; b[i] = 0; }
}

__global__ void count_kernel(const int* __restrict__ dst, int E, int* __restrict__ deg) {
    int i = blockIdx.x * blockDim.x + threadIdx.x;
    if (i < E) atomicAdd(&deg[dst[i]], 1);
}

__global__ void scan_p1(const int* __restrict__ deg, int* __restrict__ rowptr,
                        int* __restrict__ bsum, int n) {
    __shared__ int sh[1024];
    int i = blockIdx.x * 1024 + threadIdx.x;
    int v = (i < n) ? deg[i] : 0;
    sh[threadIdx.x] = v;
    __syncthreads();
    for (int off = 1; off < 1024; off <<= 1) {
        int t = (threadIdx.x >= off) ? sh[threadIdx.x - off] : 0;
        __syncthreads();
        sh[threadIdx.x] += t;
        __syncthreads();
    }
    if (i < n) rowptr[i] = sh[threadIdx.x] - v;
    if (threadIdx.x == 1023) bsum[blockIdx.x] = sh[1023];
}

__global__ void scan_p2(int* __restrict__ bsum, int nb) {
    __shared__ int sh[1024];
    int v = (threadIdx.x < nb) ? bsum[threadIdx.x] : 0;
    sh[threadIdx.x] = v;
    __syncthreads();
    for (int off = 1; off < 1024; off <<= 1) {
        int t = (threadIdx.x >= off) ? sh[threadIdx.x - off] : 0;
        __syncthreads();
        sh[threadIdx.x] += t;
        __syncthreads();
    }
    if (threadIdx.x < nb) bsum[threadIdx.x] = sh[threadIdx.x] - v;
}

__global__ void scan_p3(int* __restrict__ rowptr, const int* __restrict__ bsum,
                        int* __restrict__ cursor, int n, int E) {
    int i = blockIdx.x * blockDim.x + threadIdx.x;
    if (i < n) {
        int v = rowptr[i] + bsum[i >> 10];
        rowptr[i] = v;
        cursor[i] = v;
    }
    if (i == 0) rowptr[n] = E;
}

__global__ void fill_kernel(const int* __restrict__ src, const int* __restrict__ dst,
                            int E, int* __restrict__ cursor, int* __restrict__ col) {
    int i = blockIdx.x * blockDim.x + threadIdx.x;
    if (i < E) {
        int d = dst[i];
        int p = atomicAdd(&cursor[d], 1);
        col[p] = src[i];
    }
}

// ---------------------------------------------------------------------------
// Fused HEAD layer: 6 -> 32.
// gather raw x over both relations (lanes 0-5 = channels), then
// h = relu(sT@Wt + sM@Wi + x@Wr + b).
// ---------------------------------------------------------------------------
__global__ void fused_head(const float* __restrict__ x,
                           const int* __restrict__ rpt, const int* __restrict__ colt,
                           const int* __restrict__ rpi, const int* __restrict__ coli,
                           const float* __restrict__ Wt, const float* __restrict__ Wi,
                           const float* __restrict__ Wr, const float* __restrict__ b,
                           float* __restrict__ hout, int n) {
    __shared__ float sWt[6 * 32], sWi[6 * 32], sWr[6 * 32], sB[32];
    for (int i = threadIdx.x; i < 6 * 32; i += blockDim.x) {
        sWt[i] = Wt[i]; sWi[i] = Wi[i]; sWr[i] = Wr[i];
    }
    if (threadIdx.x < 32) sB[threadIdx.x] = b[threadIdx.x];
    __syncthreads();

    int node = blockIdx.x * (blockDim.x >> 5) + (threadIdx.x >> 5);
    if (node >= n) return;
    int lane = threadIdx.x & 31;

    float sT = 0.f, sM = 0.f;

    int b0 = rpt[node], e0 = rpt[node + 1];
    for (int e = b0; e < e0; e++) {
        int s = colt[e];
        if (lane < 6) sT += x[s * 6 + lane];
    }

    int b1 = rpi[node], e1 = rpi[node + 1];
    int e = b1;
    for (; e + 32 <= e1; e += 32) {
        int idx = coli[e + lane];
#pragma unroll
        for (int k = 0; k < 32; k++) {
            int s = __shfl_sync(0xffffffffu, idx, k);
            if (lane < 6) sM += x[s * 6 + lane];
        }
    }
    if (e < e1) {
        int rem = e1 - e;
        int idx = (lane < rem) ? coli[e + lane] : 0;
        for (int k = 0; k < rem; k++) {
            int s = __shfl_sync(0xffffffffu, idx, k);
            if (lane < 6) sM += x[s * 6 + lane];
        }
    }
    sM *= 1.0f / fmaxf((float)(e1 - b1), 1.0f);

    float xv = (lane < 6) ? x[node * 6 + lane] : 0.f;

    float acc = sB[lane];
#pragma unroll
    for (int ci = 0; ci < 6; ci++) {
        float t = __shfl_sync(0xffffffffu, sT, ci);
        float m = __shfl_sync(0xffffffffu, sM, ci);
        float r = __shfl_sync(0xffffffffu, xv, ci);
        acc += t * sWt[ci * 32 + lane] + m * sWi[ci * 32 + lane] + r * sWr[ci * 32 + lane];
    }
    hout[node * 32 + lane] = fmaxf(acc, 0.f);
}

// ---------------------------------------------------------------------------
// Fused HIDDEN layer: 32 -> 32 with residual.
// gather raw h (fp32, lane=channel, one 128B row per edge), combine in-reg.
// ---------------------------------------------------------------------------
__global__ void fused_hidden(const float* __restrict__ h,
                             const int* __restrict__ rpt, const int* __restrict__ colt,
                             const int* __restrict__ rpi, const int* __restrict__ coli,
                             const float* __restrict__ Wt, const float* __restrict__ Wi,
                             const float* __restrict__ Wr, const float* __restrict__ b,
                             float* __restrict__ hout, int n) {
    __shared__ float sWt[32 * 32], sWi[32 * 32], sWr[32 * 32], sB[32];
    for (int i = threadIdx.x; i < 32 * 32; i += blockDim.x) {
        sWt[i] = Wt[i]; sWi[i] = Wi[i]; sWr[i] = Wr[i];
    }
    if (threadIdx.x < 32) sB[threadIdx.x] = b[threadIdx.x];
    __syncthreads();

    int node = blockIdx.x * (blockDim.x >> 5) + (threadIdx.x >> 5);
    if (node >= n) return;
    int lane = threadIdx.x & 31;

    float sT = 0.f, sM = 0.f;

    int b0 = rpt[node], e0 = rpt[node + 1];
    for (int e = b0; e < e0; e++) {
        int s = colt[e];
        sT += h[s * 32 + lane];
    }

    int b1 = rpi[node], e1 = rpi[node + 1];
    int e = b1;
    for (; e + 32 <= e1; e += 32) {
        int idx = coli[e + lane];
#pragma unroll
        for (int k = 0; k < 32; k++) {
            int s = __shfl_sync(0xffffffffu, idx, k);
            sM += h[s * 32 + lane];
        }
    }
    if (e < e1) {
        int rem = e1 - e;
        int idx = (lane < rem) ? coli[e + lane] : 0;
        for (int k = 0; k < rem; k++) {
            int s = __shfl_sync(0xffffffffu, idx, k);
            sM += h[s * 32 + lane];
        }
    }
    sM *= 1.0f / fmaxf((float)(e1 - b1), 1.0f);

    float hv = h[node * 32 + lane];

    float acc = sB[lane];
#pragma unroll
    for (int ci = 0; ci < 32; ci++) {
        float t = __shfl_sync(0xffffffffu, sT, ci);
        float m = __shfl_sync(0xffffffffu, sM, ci);
        float r = __shfl_sync(0xffffffffu, hv, ci);
        acc += t * sWt[ci * 32 + lane] + m * sWi[ci * 32 + lane] + r * sWr[ci * 32 + lane];
    }
    hout[node * 32 + lane] = fmaxf(acc, 0.f) + hv;   // residual
}

// ---------------------------------------------------------------------------
// Fused LAST layer: 32 -> 64, out = relu(sT@Wt + sM@Wi + h@Wr + b) + h@Wp.
// lane handles output channels {lane, lane+32}.
// ---------------------------------------------------------------------------
__global__ void fused_last(const float* __restrict__ h,
                           const int* __restrict__ rpt, const int* __restrict__ colt,
                           const int* __restrict__ rpi, const int* __restrict__ coli,
                           const float* __restrict__ Wt, const float* __restrict__ Wi,
                           const float* __restrict__ Wr, const float* __restrict__ b,
                           const float* __restrict__ Wp,
                           float* __restrict__ out, int n) {
    __shared__ float sWt[32 * 64], sWi[32 * 64], sWr[32 * 64], sWp[32 * 64], sB[64];
    for (int i = threadIdx.x; i < 32 * 64; i += blockDim.x) {
        sWt[i] = Wt[i]; sWi[i] = Wi[i]; sWr[i] = Wr[i]; sWp[i] = Wp[i];
    }
    if (threadIdx.x < 64) sB[threadIdx.x] = b[threadIdx.x];
    __syncthreads();

    int node = blockIdx.x * (blockDim.x >> 5) + (threadIdx.x >> 5);
    if (node >= n) return;
    int lane = threadIdx.x & 31;

    float sT = 0.f, sM = 0.f;

    int b0 = rpt[node], e0 = rpt[node + 1];
    for (int e = b0; e < e0; e++) {
        int s = colt[e];
        sT += h[s * 32 + lane];
    }

    int b1 = rpi[node], e1 = rpi[node + 1];
    int e = b1;
    for (; e + 32 <= e1; e += 32) {
        int idx = coli[e + lane];
#pragma unroll
        for (int k = 0; k < 32; k++) {
            int s = __shfl_sync(0xffffffffu, idx, k);
            sM += h[s * 32 + lane];
        }
    }
    if (e < e1) {
        int rem = e1 - e;
        int idx = (lane < rem) ? coli[e + lane] : 0;
        for (int k = 0; k < rem; k++) {
            int s = __shfl_sync(0xffffffffu, idx, k);
            sM += h[s * 32 + lane];
        }
    }
    sM *= 1.0f / fmaxf((float)(e1 - b1), 1.0f);

    float hv = h[node * 32 + lane];

    float acc0 = sB[lane], acc1 = sB[lane + 32];
    float p0 = 0.f, p1 = 0.f;
#pragma unroll
    for (int ci = 0; ci < 32; ci++) {
        float t = __shfl_sync(0xffffffffu, sT, ci);
        float m = __shfl_sync(0xffffffffu, sM, ci);
        float r = __shfl_sync(0xffffffffu, hv, ci);
        acc0 += t * sWt[ci * 64 + lane]      + m * sWi[ci * 64 + lane]      + r * sWr[ci * 64 + lane];
        acc1 += t * sWt[ci * 64 + lane + 32] + m * sWi[ci * 64 + lane + 32] + r * sWr[ci * 64 + lane + 32];
        p0   += r * sWp[ci * 64 + lane];
        p1   += r * sWp[ci * 64 + lane + 32];
    }
    out[node * 64 + lane]      = fmaxf(acc0, 0.f) + p0;
    out[node * 64 + lane + 32] = fmaxf(acc1, 0.f) + p1;
}

// ---------------------------------------------------------------------------
// Launch
// ---------------------------------------------------------------------------
extern "C" void kernel_launch(void* const* d_in, const int* in_sizes, int n_in,
                              void* d_out, int out_size) {
    const float* x        = (const float*)d_in[0];
    const int*   ei_t     = (const int*)d_in[1];
    const int*   ei_i     = (const int*)d_in[2];
    const float* head_Wt  = (const float*)d_in[3];
    const float* head_Wi  = (const float*)d_in[4];
    const float* head_Wr  = (const float*)d_in[5];
    const float* head_b   = (const float*)d_in[6];
    const float* blk_Wt   = (const float*)d_in[7];
    const float* blk_Wi   = (const float*)d_in[8];
    const float* blk_Wr   = (const float*)d_in[9];
    const float* blk_b    = (const float*)d_in[10];
    const float* last_Wt  = (const float*)d_in[11];
    const float* last_Wi  = (const float*)d_in[12];
    const float* last_Wr  = (const float*)d_in[13];
    const float* last_b   = (const float*)d_in[14];
    const float* last_proj= (const float*)d_in[15];

    const int n  = in_sizes[0] / 6;      // 100000
    const int Et = in_sizes[1] / 2;      // 100000
    const int Ei = in_sizes[2] / 2;      // 3200000

    float *h, *h2;
    int *degt, *degi, *rpt, *rpi, *colt, *coli, *bst, *bsi;
    cudaGetSymbolAddress((void**)&h,    g_h);
    cudaGetSymbolAddress((void**)&h2,   g_h2);
    cudaGetSymbolAddress((void**)&degt, g_deg_t);
    cudaGetSymbolAddress((void**)&degi, g_deg_i);
    cudaGetSymbolAddress((void**)&rpt,  g_rpt);
    cudaGetSymbolAddress((void**)&rpi,  g_rpi);
    cudaGetSymbolAddress((void**)&bst,  g_bsum_t);
    cudaGetSymbolAddress((void**)&bsi,  g_bsum_i);
    cudaGetSymbolAddress((void**)&colt, g_col_t);
    cudaGetSymbolAddress((void**)&coli, g_col_i);

    const int T = 256;
    int nodeBlocks = (n * 32 + T - 1) / T;
    int nb = (n + 1023) / 1024;

    // --- CSR build (identical to 678us champion) ---
    zero2_kernel<<<(n + T - 1) / T, T>>>(degt, degi, n);
    count_kernel<<<(Et + T - 1) / T, T>>>(ei_t + Et, Et, degt);
    count_kernel<<<(Ei + T - 1) / T, T>>>(ei_i + Ei, Ei, degi);
    scan_p1<<<nb, 1024>>>(degt, rpt, bst, n);
    scan_p1<<<nb, 1024>>>(degi, rpi, bsi, n);
    scan_p2<<<1, 1024>>>(bst, nb);
    scan_p2<<<1, 1024>>>(bsi, nb);
    scan_p3<<<(n + T) / T, T>>>(rpt, bst, degt, n, Et);
    scan_p3<<<(n + T) / T, T>>>(rpi, bsi, degi, n, Ei);
    fill_kernel<<<(Et + T - 1) / T, T>>>(ei_t, ei_t + Et, Et, degt, colt);
    fill_kernel<<<(Ei + T - 1) / T, T>>>(ei_i, ei_i + Ei, Ei, degi, coli);

    // --- head: 6 -> 32 (fused) ---
    fused_head<<<nodeBlocks, T>>>(x, rpt, colt, rpi, coli,
                                  head_Wt, head_Wi, head_Wr, head_b, h, n);

    // --- 3 residual blocks: 32 -> 32 (fused) ---
    for (int i = 0; i < 3; i++) {
        fused_hidden<<<nodeBlocks, T>>>(h, rpt, colt, rpi, coli,
                                        blk_Wt + i * 32 * 32, blk_Wi + i * 32 * 32,
                                        blk_Wr + i * 32 * 32, blk_b + i * 32,
                                        h2, n);
        float* tmp = h; h = h2; h2 = tmp;
    }

    // --- last: 32 -> 64 (fused) ---
    fused_last<<<nodeBlocks, T>>>(h, rpt, colt, rpi, coli,
                                  last_Wt, last_Wi, last_Wr, last_b, last_proj,
                                  (float*)d_out, n);
}